// round 11
// baseline (speedup 1.0000x reference)
#include <cuda_runtime.h>
#include <cuda_bf16.h>
#include <math.h>

#define TT 64
#define BB 128
#define NN 2048

// Precomputed scratch (allocation-free: __device__ globals)
__device__ __align__(16) float g_W[TT * NN];     // 1 - beta*(1 - sigmoid(cond))  [T,N]
__device__ __align__(16) float g_decay[NN];      // 1 - al*(1-tau_s)
__device__ __align__(16) float g_decayg[NN];     // decay * (1-ga)
__device__ __align__(16) float g_leak[NN];       // (1-al)*leak_s
__device__ __align__(16) float g_rst[NN];        // (1-ga)*reVth_s
__device__ __align__(16) float g_vth[NN];        // sigmoid(Vth)

__device__ __forceinline__ float sigm_fast(float x) {
    return 1.0f / (1.0f + __expf(-x));
}

// Vectorized prep: one thread per 4 (t,n) cells of W.
__global__ void __launch_bounds__(256)
glif_prep(const float* __restrict__ alpha,
          const float* __restrict__ beta,
          const float* __restrict__ gamma,
          const float* __restrict__ tau,
          const float* __restrict__ Vth,
          const float* __restrict__ leak,
          const float* __restrict__ reVth,
          const float* __restrict__ cond) {
    int i4 = blockIdx.x * blockDim.x + threadIdx.x;   // over T*N/4
    if (i4 >= TT * NN / 4) return;
    int n4 = i4 & (NN / 4 - 1);                       // float4 index within N

    const float4 c  = reinterpret_cast<const float4*>(cond)[i4];
    const float4 bt = reinterpret_cast<const float4*>(beta)[n4];
    float4 w;
    w.x = 1.0f - sigm_fast(bt.x) * (1.0f - sigm_fast(c.x));
    w.y = 1.0f - sigm_fast(bt.y) * (1.0f - sigm_fast(c.y));
    w.z = 1.0f - sigm_fast(bt.z) * (1.0f - sigm_fast(c.z));
    w.w = 1.0f - sigm_fast(bt.w) * (1.0f - sigm_fast(c.w));
    reinterpret_cast<float4*>(g_W)[i4] = w;

    if (i4 < NN / 4) {
        const float4 av = reinterpret_cast<const float4*>(alpha)[i4];
        const float4 gv = reinterpret_cast<const float4*>(gamma)[i4];
        const float4 tv = reinterpret_cast<const float4*>(tau)[i4];
        const float4 vv = reinterpret_cast<const float4*>(Vth)[i4];
        const float4 lv = reinterpret_cast<const float4*>(leak)[i4];
        const float4 rv = reinterpret_cast<const float4*>(reVth)[i4];
        float4 dec, decg, lk, rs, vt;
        {
            float al = sigm_fast(av.x), ga = sigm_fast(gv.x);
            float d = 1.0f - al * (1.0f - sigm_fast(tv.x));
            dec.x = d; decg.x = d * (1.0f - ga);
            lk.x = (1.0f - al) * sigm_fast(lv.x);
            rs.x = (1.0f - ga) * sigm_fast(rv.x);
            vt.x = sigm_fast(vv.x);
        }
        {
            float al = sigm_fast(av.y), ga = sigm_fast(gv.y);
            float d = 1.0f - al * (1.0f - sigm_fast(tv.y));
            dec.y = d; decg.y = d * (1.0f - ga);
            lk.y = (1.0f - al) * sigm_fast(lv.y);
            rs.y = (1.0f - ga) * sigm_fast(rv.y);
            vt.y = sigm_fast(vv.y);
        }
        {
            float al = sigm_fast(av.z), ga = sigm_fast(gv.z);
            float d = 1.0f - al * (1.0f - sigm_fast(tv.z));
            dec.z = d; decg.z = d * (1.0f - ga);
            lk.z = (1.0f - al) * sigm_fast(lv.z);
            rs.z = (1.0f - ga) * sigm_fast(rv.z);
            vt.z = sigm_fast(vv.z);
        }
        {
            float al = sigm_fast(av.w), ga = sigm_fast(gv.w);
            float d = 1.0f - al * (1.0f - sigm_fast(tv.w));
            dec.w = d; decg.w = d * (1.0f - ga);
            lk.w = (1.0f - al) * sigm_fast(lv.w);
            rs.w = (1.0f - ga) * sigm_fast(rv.w);
            vt.w = sigm_fast(vv.w);
        }
        reinterpret_cast<float4*>(g_decay)[i4]  = dec;
        reinterpret_cast<float4*>(g_decayg)[i4] = decg;
        reinterpret_cast<float4*>(g_leak)[i4]   = lk;
        reinterpret_cast<float4*>(g_rst)[i4]    = rs;
        reinterpret_cast<float4*>(g_vth)[i4]    = vt;
    }
}

// Main scan: one thread owns 2 consecutive neurons for one batch row,
// carries (v,y) in registers across T=64 steps. Prefetch depth 1.
// tx loads are L2-ALLOCATING (__ldg): tx (64MB) fits in GB300's 126MB L2 and
// stays resident across graph replays -> reads at L2-hit latency, not DRAM.
// out stores are WRITE-THROUGH NO-ALLOCATE (__stwt): the spike stream has
// zero reuse, so allocating L2 lines for it only evicts tx.
__global__ void __launch_bounds__(128)
glif_main(const float* __restrict__ tx, float* __restrict__ out) {
    const int tid = blockIdx.x * blockDim.x + threadIdx.x;  // 0 .. B*N/2-1
    const int n2  = tid & (NN / 2 - 1);                     // float2 group within N

    const float2* __restrict__ tx2 = reinterpret_cast<const float2*>(tx);
    const float2* __restrict__ W2  = reinterpret_cast<const float2*>(g_W);
    float2* __restrict__ out2      = reinterpret_cast<float2*>(out);

    const float2 dec  = reinterpret_cast<const float2*>(g_decay)[n2];
    const float2 decg = reinterpret_cast<const float2*>(g_decayg)[n2];
    const float2 lk   = reinterpret_cast<const float2*>(g_leak)[n2];
    const float2 rs   = reinterpret_cast<const float2*>(g_rst)[n2];
    const float2 vth  = reinterpret_cast<const float2*>(g_vth)[n2];

    const float ddx = decg.x - dec.x;   // dv = fma(y, ddx, dec)
    const float ddy = decg.y - dec.y;

    float2 v = make_float2(0.f, 0.f);
    float2 y = make_float2(0.f, 0.f);

    const int stride = BB * NN / 2;   // float2 stride per timestep
    const int wstr   = NN / 2;

    // Prefetch t=0 (L2-allocating)
    float2 x = __ldg(&tx2[tid]);
    float2 w = __ldg(&W2[n2]);

    #pragma unroll 8
    for (int t = 0; t < TT; ++t) {
        // Prefetch t+1 before touching the dependency chain
        float2 xn, wn;
        if (t + 1 < TT) {
            xn = __ldg(&tx2[(t + 1) * stride + tid]);
            wn = __ldg(&W2[(t + 1) * wstr + n2]);
        }

        // lane 0
        {
            float dv = fmaf(y.x, ddx, dec.x);
            float c  = fmaf(y.x, -rs.x, fmaf(x.x, w.x, -lk.x));
            v.x = fmaf(dv, v.x, c);
            y.x = (v.x > vth.x) ? 1.0f : 0.0f;
        }
        // lane 1
        {
            float dv = fmaf(y.y, ddy, dec.y);
            float c  = fmaf(y.y, -rs.y, fmaf(x.y, w.y, -lk.y));
            v.y = fmaf(dv, v.y, c);
            y.y = (v.y > vth.y) ? 1.0f : 0.0f;
        }

        __stwt(&out2[t * stride + tid], y);
        x = xn;
        w = wn;
    }
}

extern "C" void kernel_launch(void* const* d_in, const int* in_sizes, int n_in,
                              void* d_out, int out_size) {
    // metadata order: tx, alpha, beta, gamma, tau, Vth, leak, reVth, conduct
    const float* tx    = (const float*)d_in[0];
    const float* alpha = (const float*)d_in[1];
    const float* beta  = (const float*)d_in[2];
    const float* gamma = (const float*)d_in[3];
    const float* tau   = (const float*)d_in[4];
    const float* Vth   = (const float*)d_in[5];
    const float* leak  = (const float*)d_in[6];
    const float* reVth = (const float*)d_in[7];
    const float* cond  = (const float*)d_in[8];
    float* out = (float*)d_out;

    {
        int total = TT * NN / 4;   // 32768 threads
        int blk = 256;
        glif_prep<<<(total + blk - 1) / blk, blk>>>(alpha, beta, gamma, tau,
                                                    Vth, leak, reVth, cond);
    }
    {
        int total = BB * NN / 2;   // 131072 threads
        int blk = 128;
        glif_main<<<total / blk, blk>>>(tx, out);
    }
}

// round 13
// speedup vs baseline: 1.0655x; 1.0655x over previous
#include <cuda_runtime.h>
#include <cuda_bf16.h>
#include <math.h>

#define TT 64
#define BB 128
#define NN 2048

// Single fused kernel: no prep pass, no inter-kernel gap. Each thread owns
// 2 consecutive neurons of one batch row, carries (v,y) in registers across
// T=64 steps, and computes W[t,n] = 1 - beta*(1 - sigmoid(cond[t,n])) INLINE
// (cond is 512KB -> L2-resident; MUFU cost ~35% pipe, hidden under memory).
// tx loads are L2-allocating (__ldg): tx (64MB) fits in the 126MB L2 and
// stays resident across graph replays. out stores evict-first (__stcs).

__device__ __forceinline__ float sigm_fast(float x) {
    return __fdividef(1.0f, 1.0f + __expf(-x));
}

__global__ void __launch_bounds__(128)
glif_fused(const float* __restrict__ tx,
           const float* __restrict__ alpha,
           const float* __restrict__ beta,
           const float* __restrict__ gamma,
           const float* __restrict__ tau,
           const float* __restrict__ Vth,
           const float* __restrict__ leak,
           const float* __restrict__ reVth,
           const float* __restrict__ cond,
           float* __restrict__ out) {
    const int tid = blockIdx.x * blockDim.x + threadIdx.x;  // 0 .. B*N/2-1
    const int n2  = tid & (NN / 2 - 1);                     // float2 group within N

    const float2* __restrict__ tx2 = reinterpret_cast<const float2*>(tx);
    const float2* __restrict__ cd2 = reinterpret_cast<const float2*>(cond);
    float2* __restrict__ out2      = reinterpret_cast<float2*>(out);

    // Per-neuron fused constants (computed once per thread; ~30 MUFU total)
    const float2 av = __ldg(&reinterpret_cast<const float2*>(alpha)[n2]);
    const float2 bv = __ldg(&reinterpret_cast<const float2*>(beta)[n2]);
    const float2 gv = __ldg(&reinterpret_cast<const float2*>(gamma)[n2]);
    const float2 tv = __ldg(&reinterpret_cast<const float2*>(tau)[n2]);
    const float2 vv = __ldg(&reinterpret_cast<const float2*>(Vth)[n2]);
    const float2 lv = __ldg(&reinterpret_cast<const float2*>(leak)[n2]);
    const float2 rv = __ldg(&reinterpret_cast<const float2*>(reVth)[n2]);

    float decx, decy, ddx, ddy, lkx, lky, rsx, rsy, vthx, vthy, bex, bey, obx, oby;
    {
        float al = sigm_fast(av.x), ga = sigm_fast(gv.x);
        float d  = 1.0f - al * (1.0f - sigm_fast(tv.x));
        decx = d;
        ddx  = d * (1.0f - ga) - d;          // decg - dec
        lkx  = (1.0f - al) * sigm_fast(lv.x);
        rsx  = (1.0f - ga) * sigm_fast(rv.x);
        vthx = sigm_fast(vv.x);
        bex  = sigm_fast(bv.x);
        obx  = 1.0f - bex;                   // w = fma(be, s, 1-be)
    }
    {
        float al = sigm_fast(av.y), ga = sigm_fast(gv.y);
        float d  = 1.0f - al * (1.0f - sigm_fast(tv.y));
        decy = d;
        ddy  = d * (1.0f - ga) - d;
        lky  = (1.0f - al) * sigm_fast(lv.y);
        rsy  = (1.0f - ga) * sigm_fast(rv.y);
        vthy = sigm_fast(vv.y);
        bey  = sigm_fast(bv.y);
        oby  = 1.0f - bey;
    }

    float2 v = make_float2(0.f, 0.f);
    float2 y = make_float2(0.f, 0.f);

    const int stride = BB * NN / 2;   // float2 stride per timestep
    const int wstr   = NN / 2;

    // Prefetch t=0
    float2 x = __ldg(&tx2[tid]);
    float2 c = __ldg(&cd2[n2]);

    #pragma unroll 8
    for (int t = 0; t < TT; ++t) {
        // Prefetch t+1 before touching the dependency chain
        float2 xn, cn;
        if (t + 1 < TT) {
            xn = __ldg(&tx2[(t + 1) * stride + tid]);
            cn = __ldg(&cd2[(t + 1) * wstr + n2]);
        }

        // Inline W: w = 1 - be*(1 - sigmoid(c)) = fma(be, sigm(c), 1-be)
        const float wx = fmaf(bex, sigm_fast(c.x), obx);
        const float wy = fmaf(bey, sigm_fast(c.y), oby);

        // lane 0
        {
            float dv = fmaf(y.x, ddx, decx);
            float cc = fmaf(y.x, -rsx, fmaf(x.x, wx, -lkx));
            v.x = fmaf(dv, v.x, cc);
            y.x = (v.x > vthx) ? 1.0f : 0.0f;
        }
        // lane 1
        {
            float dv = fmaf(y.y, ddy, decy);
            float cc = fmaf(y.y, -rsy, fmaf(x.y, wy, -lky));
            v.y = fmaf(dv, v.y, cc);
            y.y = (v.y > vthy) ? 1.0f : 0.0f;
        }

        __stcs(&out2[t * stride + tid], y);
        x = xn;
        c = cn;
    }
}

extern "C" void kernel_launch(void* const* d_in, const int* in_sizes, int n_in,
                              void* d_out, int out_size) {
    // metadata order: tx, alpha, beta, gamma, tau, Vth, leak, reVth, conduct
    const float* tx    = (const float*)d_in[0];
    const float* alpha = (const float*)d_in[1];
    const float* beta  = (const float*)d_in[2];
    const float* gamma = (const float*)d_in[3];
    const float* tau   = (const float*)d_in[4];
    const float* Vth   = (const float*)d_in[5];
    const float* leak  = (const float*)d_in[6];
    const float* reVth = (const float*)d_in[7];
    const float* cond  = (const float*)d_in[8];
    float* out = (float*)d_out;

    int total = BB * NN / 2;   // 131072 threads
    int blk = 128;
    glif_fused<<<total / blk, blk>>>(tx, alpha, beta, gamma, tau, Vth, leak,
                                     reVth, cond, out);
}